// round 13
// baseline (speedup 1.0000x reference)
#include <cuda_runtime.h>
#include <cuda_bf16.h>
#include <cstdint>

#define S_DIM 4096
#define E_DIM 1024
#define H_DIM 8
#define HE_DIM 8192
typedef __nv_bfloat16 bf16;

// ---------------- fp32 scratch ----------------------------------------------
__device__ float g_A  [(size_t)H_DIM * E_DIM * E_DIM];  // scaled+biased logits 32MB
__device__ float g_PT8[(size_t)H_DIM * E_DIM * E_DIM];  // G split-K8 partials, then PT partials
__device__ float g_O  [(size_t)S_DIM * E_DIM];
__device__ float g_LN1[(size_t)S_DIM * E_DIM];
__device__ float g_FN [(size_t)S_DIM * E_DIM];
__device__ float g_u32p[32 * E_DIM];
__device__ float g_u  [E_DIM];
__device__ float g_qbar[H_DIM * E_DIM];   // qbar + 4096*bq (folded)
__device__ float g_kbar[H_DIM * E_DIM];
__device__ float g_rowm[H_DIM * E_DIM];
__device__ float g_rowi[H_DIM * E_DIM];
__device__ float g_r  [H_DIM * E_DIM];
__device__ float g_c  [E_DIM];

// ---------------- bf16 hi/lo operand buffers ---------------------------------
__device__ bf16 b_xh [(size_t)S_DIM * E_DIM],  b_xl [(size_t)S_DIM * E_DIM];
__device__ bf16 b_xTh[(size_t)E_DIM * S_DIM],  b_xTl[(size_t)E_DIM * S_DIM];
__device__ bf16 b_Gh [(size_t)E_DIM * E_DIM],  b_Gl [(size_t)E_DIM * E_DIM];
__device__ bf16 b_Wkh[(size_t)H_DIM * E_DIM * E_DIM], b_Wkl[(size_t)H_DIM * E_DIM * E_DIM];
__device__ bf16 b_Wqh[(size_t)H_DIM * E_DIM * E_DIM], b_Wql[(size_t)H_DIM * E_DIM * E_DIM];
__device__ bf16 b_Th [(size_t)H_DIM * E_DIM * E_DIM], b_Tl [(size_t)H_DIM * E_DIM * E_DIM];
__device__ bf16 b_ATh[(size_t)H_DIM * E_DIM * E_DIM], b_ATl[(size_t)H_DIM * E_DIM * E_DIM];
__device__ bf16 b_WvTh[(size_t)H_DIM * E_DIM * E_DIM], b_WvTl[(size_t)H_DIM * E_DIM * E_DIM];
__device__ bf16 b_Mh [(size_t)H_DIM * E_DIM * E_DIM], b_Ml [(size_t)H_DIM * E_DIM * E_DIM];
__device__ bf16 b_Wzh[(size_t)H_DIM * E_DIM * E_DIM], b_Wzl[(size_t)H_DIM * E_DIM * E_DIM];
__device__ bf16 b_PTh[(size_t)E_DIM * E_DIM],  b_PTl[(size_t)E_DIM * E_DIM];
__device__ bf16 b_L1h[(size_t)S_DIM * E_DIM],  b_L1l[(size_t)S_DIM * E_DIM];
__device__ bf16 b_Wfh[(size_t)E_DIM * E_DIM],  b_Wfl[(size_t)E_DIM * E_DIM];

// ---------------- helpers ----------------------------------------------------
static __device__ __forceinline__ uint32_t s2u(const void* p) {
    uint32_t a;
    asm("{ .reg .u64 t; cvta.to.shared.u64 t, %1; cvt.u32.u64 %0, t; }"
        : "=r"(a) : "l"(p));
    return a;
}
static __device__ __forceinline__ uint32_t pack_bf(float a, float b) {
    uint32_t r;
    asm("cvt.rn.bf16x2.f32 %0, %1, %2;" : "=r"(r) : "f"(b), "f"(a));
    return r;
}
static __device__ __forceinline__ void ldsm4(uint32_t* r, uint32_t addr) {
    asm volatile("ldmatrix.sync.aligned.m8n8.x4.shared.b16 {%0,%1,%2,%3}, [%4];"
                 : "=r"(r[0]), "=r"(r[1]), "=r"(r[2]), "=r"(r[3]) : "r"(addr));
}
static __device__ __forceinline__ void mma16816(float* d, const uint32_t* a,
                                                uint32_t b0, uint32_t b1) {
    asm volatile(
        "mma.sync.aligned.m16n8k16.row.col.f32.bf16.bf16.f32 "
        "{%0,%1,%2,%3},{%4,%5,%6,%7},{%8,%9},{%0,%1,%2,%3};"
        : "+f"(d[0]), "+f"(d[1]), "+f"(d[2]), "+f"(d[3])
        : "r"(a[0]), "r"(a[1]), "r"(a[2]), "r"(a[3]), "r"(b0), "r"(b1));
}
static __device__ __forceinline__ void cp16(uint32_t dst, const void* src) {
    asm volatile("cp.async.cg.shared.global [%0], [%1], 16;"
                 :: "r"(dst), "l"(src));
}

// ============================================================================
// bf16 hi/lo cp.async GEMM (NT): C = (A.B^T + eA⊗eC + eB⊗eD)*alpha + bn
// CTA 128x128, BK=32, 128 threads (4 warps 2x2, warp tile 64x64), 3 stages.
// (R7/R10/R11 core — best measured config)
// ============================================================================
#define STAGEB 32768
#define SMEMB  (3 * STAGEB)

struct GemmP {
    const bf16 *Ah, *Al; long long As; int lda;
    const bf16 *Bh, *Bl; long long Bs; int ldb;
    float* Cf; bf16 *Ch, *Cl; long long Cs; int ldc;
    const float* bn;
    const float *eA, *eB, *eC, *eD; int eS;
    float alpha;
    int K;
    int zoff;
};

static __device__ __forceinline__ void issue_stage(
    uint32_t sbase, int slot,
    const bf16* __restrict__ Ah, const bf16* __restrict__ Al, int lda,
    const bf16* __restrict__ Bh, const bf16* __restrict__ Bl, int ldb,
    int k0, int tid) {
    uint32_t st = sbase + (uint32_t)slot * STAGEB;
#pragma unroll
    for (int i = 0; i < 16; i++) {
        int idx = tid + i * 128;              // 0..2047
        int half = idx >> 10;                 // 0 = A, 1 = B
        int r = (idx >> 3) & 127;
        int c = idx & 7;                      // chunk: 0-3 hi, 4-7 lo
        const bf16* base;
        int ld;
        if (half == 0) { base = (c < 4) ? Ah : Al; ld = lda; }
        else           { base = (c < 4) ? Bh : Bl; ld = ldb; }
        const char* src = (const char*)(base + (size_t)r * ld + k0) + (c & 3) * 16;
        uint32_t dst = st + (uint32_t)half * 16384u + (uint32_t)r * 128u
                     + (uint32_t)((c ^ (r & 7)) << 4);
        cp16(dst, src);
    }
}

__global__ __launch_bounds__(128, 2) void k_gemm(GemmP p) {
    extern __shared__ char smem[];
    const int tid = threadIdx.x;
    const int w = tid >> 5, l = tid & 31;
    const int wm = (w >> 1) * 64, wn = (w & 1) * 64;
    const int m0 = blockIdx.y * 128, n0 = blockIdx.x * 128;
    const int z = blockIdx.z + p.zoff;
    const uint32_t s0 = s2u(smem);

    const bf16* Abh = p.Ah + (size_t)z * p.As + (size_t)m0 * p.lda;
    const bf16* Abl = p.Al + (size_t)z * p.As + (size_t)m0 * p.lda;
    const bf16* Bbh = p.Bh + (size_t)z * p.Bs + (size_t)n0 * p.ldb;
    const bf16* Bbl = p.Bl + (size_t)z * p.Bs + (size_t)n0 * p.ldb;

    const uint32_t axor = (uint32_t)(l & 7);
    const uint32_t arow = (uint32_t)(wm + (l & 15));
    const uint32_t asel = (uint32_t)(l >> 4);
    const uint32_t brow = (uint32_t)(wn + (l & 7) + ((l >> 4) & 1) * 8);
    const uint32_t bsel = (uint32_t)((l >> 3) & 1);

    float acc[4][8][4];
#pragma unroll
    for (int t = 0; t < 4; t++)
#pragma unroll
        for (int j = 0; j < 8; j++)
#pragma unroll
            for (int r = 0; r < 4; r++) acc[t][j][r] = 0.f;

    const int NC = p.K >> 5;
    issue_stage(s0, 0, Abh, Abl, p.lda, Bbh, Bbl, p.ldb, 0, tid);
    asm volatile("cp.async.commit_group;" ::: "memory");
    issue_stage(s0, 1, Abh, Abl, p.lda, Bbh, Bbl, p.ldb, 32, tid);
    asm volatile("cp.async.commit_group;" ::: "memory");

    for (int c = 0; c < NC; c++) {
        asm volatile("cp.async.wait_group 1;" ::: "memory");
        __syncthreads();
        if (c + 2 < NC)
            issue_stage(s0, (c + 2) % 3, Abh, Abl, p.lda, Bbh, Bbl, p.ldb,
                        (c + 2) * 32, tid);
        asm volatile("cp.async.commit_group;" ::: "memory");

        uint32_t st = s0 + (uint32_t)(c % 3) * STAGEB;
#pragma unroll
        for (int ks = 0; ks < 2; ks++) {
            uint32_t bh[4][4], bl[4][4];
#pragma unroll
            for (int jp = 0; jp < 4; jp++) {
                uint32_t ba = st + 16384u + (brow + jp * 16u) * 128u
                            + (((2u * ks + bsel) ^ axor) << 4);
                ldsm4(bh[jp], ba);
                ldsm4(bl[jp], ba ^ 0x40u);
            }
#pragma unroll
            for (int t = 0; t < 4; t++) {
                uint32_t ah[4], al[4];
                uint32_t aa = st + (arow + t * 16u) * 128u
                            + (((2u * ks + asel) ^ axor) << 4);
                ldsm4(ah, aa);
                ldsm4(al, aa ^ 0x40u);
#pragma unroll
                for (int j = 0; j < 8; j++) {
                    uint32_t b0h = bh[j >> 1][(j & 1) * 2];
                    uint32_t b1h = bh[j >> 1][(j & 1) * 2 + 1];
                    uint32_t b0l = bl[j >> 1][(j & 1) * 2];
                    uint32_t b1l = bl[j >> 1][(j & 1) * 2 + 1];
                    mma16816(acc[t][j], ah, b0h, b1h);
                    mma16816(acc[t][j], ah, b0l, b1l);
                    mma16816(acc[t][j], al, b0h, b1h);
                }
            }
        }
    }

    float* Cf = p.Cf ? p.Cf + (size_t)z * p.Cs : (float*)0;
    bf16* Ch = p.Ch ? p.Ch + (size_t)z * p.Cs : (bf16*)0;
    bf16* Cl = p.Cl ? p.Cl + (size_t)z * p.Cs : (bf16*)0;
    const float* bn = p.bn;
    const float* eA = p.eA ? p.eA + (size_t)z * p.eS : (const float*)0;
    const float* eB = p.eB ? p.eB + (size_t)z * p.eS : (const float*)0;
    const float* eC = p.eC ? p.eC + (size_t)z * p.eS : (const float*)0;
    const float* eD = p.eD ? p.eD + (size_t)z * p.eS : (const float*)0;
    const float alpha = p.alpha;
#pragma unroll
    for (int t = 0; t < 4; t++) {
        int m = m0 + wm + t * 16 + (l >> 2);
#pragma unroll
        for (int j = 0; j < 8; j++) {
            int n = n0 + wn + j * 8 + (l & 3) * 2;
#pragma unroll
            for (int h2 = 0; h2 < 2; h2++) {
                float v0 = acc[t][j][h2 * 2], v1 = acc[t][j][h2 * 2 + 1];
                int mr = m + h2 * 8;
                if (eA) {
                    float a = eA[mr], b = eB[mr];
                    v0 += a * eC[n]     + b * eD[n];
                    v1 += a * eC[n + 1] + b * eD[n + 1];
                }
                v0 *= alpha; v1 *= alpha;
                if (bn) { v0 += bn[n]; v1 += bn[n + 1]; }
                if (Cf) *(float2*)(Cf + (size_t)mr * p.ldc + n) = make_float2(v0, v1);
                if (Ch) {
                    uint32_t hh = pack_bf(v0, v1);
                    *(uint32_t*)((char*)Ch + ((size_t)mr * p.ldc + n) * 2) = hh;
                    float l0 = v0 - __uint_as_float(hh << 16);
                    float l1 = v1 - __uint_as_float(hh & 0xFFFF0000u);
                    *(uint32_t*)((char*)Cl + ((size_t)mr * p.ldc + n) * 2) = pack_bf(l0, l1);
                }
            }
        }
    }
}

// ---------------- reductions -------------------------------------------------
static __device__ __forceinline__ float blockReduceSum256(float v) {
    __shared__ float sb[8];
#pragma unroll
    for (int o = 16; o > 0; o >>= 1) v += __shfl_xor_sync(0xffffffffu, v, o);
    __syncthreads();
    if ((threadIdx.x & 31) == 0) sb[threadIdx.x >> 5] = v;
    __syncthreads();
    float r = sb[0];
#pragma unroll
    for (int i = 1; i < 8; i++) r += sb[i];
    return r;
}
static __device__ __forceinline__ float blockReduceMax256(float v) {
    __shared__ float sb[8];
#pragma unroll
    for (int o = 16; o > 0; o >>= 1) v = fmaxf(v, __shfl_xor_sync(0xffffffffu, v, o));
    __syncthreads();
    if ((threadIdx.x & 31) == 0) sb[threadIdx.x >> 5] = v;
    __syncthreads();
    float r = sb[0];
#pragma unroll
    for (int i = 1; i < 8; i++) r = fmaxf(r, sb[i]);
    return r;
}

// ---------------- conversion / transpose kernels ------------------------------
__global__ void k_split(const float4* __restrict__ src, uint2* __restrict__ hi,
                        uint2* __restrict__ lo, int n4) {
    int i = blockIdx.x * 256 + threadIdx.x;
    if (i >= n4) return;
    float4 v = src[i];
    uint32_t h0 = pack_bf(v.x, v.y), h1 = pack_bf(v.z, v.w);
    float lx = v.x - __uint_as_float(h0 << 16);
    float ly = v.y - __uint_as_float(h0 & 0xFFFF0000u);
    float lz = v.z - __uint_as_float(h1 << 16);
    float lw = v.w - __uint_as_float(h1 & 0xFFFF0000u);
    hi[i] = make_uint2(h0, h1);
    lo[i] = make_uint2(pack_bf(lx, ly), pack_bf(lz, lw));
}

__global__ void k_trans_split(const float* __restrict__ src,
                              bf16* __restrict__ hi, bf16* __restrict__ lo,
                              int R, int C, long long ss, long long ds) {
    __shared__ float t[32][33];
    src += (size_t)blockIdx.z * ss;
    hi += (size_t)blockIdx.z * ds;
    lo += (size_t)blockIdx.z * ds;
    int c0 = blockIdx.x * 32, r0 = blockIdx.y * 32;
#pragma unroll
    for (int i = 0; i < 32; i += 8)
        t[threadIdx.y + i][threadIdx.x] =
            src[(size_t)(r0 + threadIdx.y + i) * C + c0 + threadIdx.x];
    __syncthreads();
#pragma unroll
    for (int i = 0; i < 32; i += 8) {
        float v = t[threadIdx.x][threadIdx.y + i];
        bf16 h = __float2bfloat16_rn(v);
        size_t o = (size_t)(c0 + threadIdx.y + i) * R + r0 + threadIdx.x;
        hi[o] = h;
        lo[o] = __float2bfloat16_rn(v - __bfloat162float(h));
    }
}

// row max + 1/sum(exp) of logits, rows [rowbase, rowbase+grid)
__global__ __launch_bounds__(256, 4) void k_rowstat(int rowbase) {
    int row = rowbase + blockIdx.x;
    const float* p = g_A + (size_t)row * E_DIM;
    int tid = threadIdx.x;
    float v[4];
    float m = -1e30f;
#pragma unroll
    for (int i = 0; i < 4; i++) { v[i] = p[tid + i * 256]; m = fmaxf(m, v[i]); }
    m = blockReduceMax256(m);
    float s = 0;
#pragma unroll
    for (int i = 0; i < 4; i++) s += __expf(v[i] - m);
    s = blockReduceSum256(s);
    if (tid == 0) { g_rowm[row] = m; g_rowi[row] = 1.0f / s; }
}

// AT[f,e] = exp(A[e,f]-m[e])*inv[e], hi/lo split, heads [hbase, hbase+grid.z)
__global__ void k_transexp(bf16* __restrict__ hi, bf16* __restrict__ lo, int hbase) {
    __shared__ float t[32][33];
    int h = hbase + blockIdx.z;
    const float* src = g_A + (size_t)h * E_DIM * E_DIM;
    bf16* hih = hi + (size_t)h * E_DIM * E_DIM;
    bf16* loh = lo + (size_t)h * E_DIM * E_DIM;
    int f0 = blockIdx.x * 32, e0 = blockIdx.y * 32;
#pragma unroll
    for (int i = 0; i < 32; i += 8) {
        int e = e0 + threadIdx.y + i;
        float m = g_rowm[h * E_DIM + e], inv = g_rowi[h * E_DIM + e];
        float v = src[(size_t)e * E_DIM + f0 + threadIdx.x];
        t[threadIdx.y + i][threadIdx.x] = __expf(v - m) * inv;
    }
    __syncthreads();
#pragma unroll
    for (int i = 0; i < 32; i += 8) {
        float v = t[threadIdx.x][threadIdx.y + i];
        bf16 hh = __float2bfloat16_rn(v);
        size_t o = (size_t)(f0 + threadIdx.y + i) * E_DIM + e0 + threadIdx.x;
        hih[o] = hh;
        loh[o] = __float2bfloat16_rn(v - __bfloat162float(hh));
    }
}

__global__ void k_reduce_split(const float* __restrict__ src, int Z, int total,
                               bf16* __restrict__ hi, bf16* __restrict__ lo) {
    int i = blockIdx.x * 256 + threadIdx.x;
    if (i >= total) return;
    float s = 0;
    for (int zz = 0; zz < Z; zz++) s += src[(size_t)zz * total + i];
    bf16 h = __float2bfloat16_rn(s);
    hi[i] = h;
    lo[i] = __float2bfloat16_rn(s - __bfloat162float(h));
}

// ---------------- small algebra kernels ---------------------------------------
__global__ void k_usum1(const float* __restrict__ x) {
    int e = blockIdx.x * 256 + threadIdx.x;
    int zc = blockIdx.y;
    float s = 0;
    for (int si = zc * 128; si < zc * 128 + 128; si++) s += x[(size_t)si * E_DIM + e];
    g_u32p[zc * E_DIM + e] = s;
}
__global__ void k_usum2() {
    int e = blockIdx.x * 256 + threadIdx.x;
    float s = 0;
    for (int zc = 0; zc < 32; zc++) s += g_u32p[zc * E_DIM + e];
    g_u[e] = s;
}
__global__ void k_qkbar(const float* __restrict__ Wq, const float* __restrict__ Wk,
                        const float* __restrict__ bq) {
    int f = blockIdx.x, h = blockIdx.y;
    const float* Wrow = (blockIdx.z == 0 ? Wq : Wk) + ((size_t)h * E_DIM + f) * E_DIM;
    float s = 0;
    for (int i = threadIdx.x; i < E_DIM; i += 256) s += g_u[i] * Wrow[i];
    s = blockReduceSum256(s);
    if (threadIdx.x == 0) {
        if (blockIdx.z == 0) g_qbar[h * E_DIM + f] = s + 4096.0f * bq[h * E_DIM + f];
        else                 g_kbar[h * E_DIM + f] = s;
    }
}

__global__ void k_rvec(const bf16* __restrict__ ATh, const bf16* __restrict__ ATl,
                       const float* __restrict__ bv) {
    int f = blockIdx.x, h = blockIdx.y;
    const bf16* ph = ATh + ((size_t)h * E_DIM + f) * E_DIM;
    const bf16* pl = ATl + ((size_t)h * E_DIM + f) * E_DIM;
    const float* bvh = bv + h * E_DIM;
    float s = 0;
    for (int e = threadIdx.x; e < E_DIM; e += 256)
        s += (__bfloat162float(ph[e]) + __bfloat162float(pl[e])) * bvh[e];
    s = blockReduceSum256(s);
    if (threadIdx.x == 0) g_r[h * E_DIM + f] = s;
}
__global__ void k_cvec(const float* __restrict__ Wz, const float* __restrict__ bz) {
    int o = blockIdx.x;
    const float* wrow = Wz + (size_t)o * HE_DIM;
    float s = 0;
    for (int i = threadIdx.x; i < HE_DIM; i += 256) s += g_r[i] * wrow[i];
    s = blockReduceSum256(s);
    if (threadIdx.x == 0) g_c[o] = bz[o] + s;
}

// LN1 = LN(O)*g1+b1 + x  (writes fp32 + bf16 hi/lo)
__global__ __launch_bounds__(256, 4)
void k_ln1(const float* __restrict__ x, const float* __restrict__ g,
           const float* __restrict__ b) {
    const size_t row = blockIdx.x;
    const int tid = threadIdx.x;
    const float* p = g_O + row * E_DIM;
    float v[4];
    float s = 0.f;
#pragma unroll
    for (int i = 0; i < 4; i++) { v[i] = p[tid + i * 256]; s += v[i]; }
    const float mean = blockReduceSum256(s) * (1.0f / E_DIM);
    float q = 0.f;
#pragma unroll
    for (int i = 0; i < 4; i++) { const float d = v[i] - mean; q += d * d; }
    const float var = blockReduceSum256(q) * (1.0f / E_DIM);
    const float rstd = rsqrtf(var + 1e-5f);
#pragma unroll
    for (int i = 0; i < 4; i++) {
        const int idx = tid + i * 256;
        float o = (v[i] - mean) * rstd * g[idx] + b[idx] + x[row * E_DIM + idx];
        g_LN1[row * E_DIM + idx] = o;
        bf16 h = __float2bfloat16_rn(o);
        b_L1h[row * E_DIM + idx] = h;
        b_L1l[row * E_DIM + idx] = __float2bfloat16_rn(o - __bfloat162float(h));
    }
}

__global__ __launch_bounds__(256, 4)
void k_ln2(const float* __restrict__ g, const float* __restrict__ b,
           float* __restrict__ out) {
    const size_t row = blockIdx.x;
    const int tid = threadIdx.x;
    const float* p = g_FN + row * E_DIM;
    float v[4];
    float s = 0.f;
#pragma unroll
    for (int i = 0; i < 4; i++) { v[i] = p[tid + i * 256]; s += v[i]; }
    const float mean = blockReduceSum256(s) * (1.0f / E_DIM);
    float q = 0.f;
#pragma unroll
    for (int i = 0; i < 4; i++) { const float d = v[i] - mean; q += d * d; }
    const float var = blockReduceSum256(q) * (1.0f / E_DIM);
    const float rstd = rsqrtf(var + 1e-5f);
#pragma unroll
    for (int i = 0; i < 4; i++) {
        const int idx = tid + i * 256;
        out[row * E_DIM + idx] =
            (v[i] - mean) * rstd * g[idx] + b[idx] + g_LN1[row * E_DIM + idx];
    }
}

// ============================================================================
// Launch — 4-stream head pipeline + parallel prep + split-K8 G + R11 tail
// (every cudaEventRecord precedes its cudaStreamWaitEvent in host order)
// ============================================================================
#define SYM(v, s) cudaGetSymbolAddress((void**)&v, s)

static cudaStream_t g_st[3];          // s1, s2, s3 (s0 = default)
static cudaEvent_t evFork, evP1, evP2, evP3, evG;
static cudaEvent_t evAT[4], evPT[4], evC;
static bool g_init = false;

extern "C" void kernel_launch(void* const* d_in, const int* in_sizes, int n_in,
                              void* d_out, int out_size) {
    (void)in_sizes; (void)n_in; (void)out_size;
    const float* x  = (const float*)d_in[0];
    const float* Wq = (const float*)d_in[1];
    const float* bq = (const float*)d_in[2];
    const float* Wk = (const float*)d_in[3];
    const float* bk = (const float*)d_in[4];
    const float* Wv = (const float*)d_in[5];
    const float* bv = (const float*)d_in[6];
    const float* Wz = (const float*)d_in[7];
    const float* bz = (const float*)d_in[8];
    const float* g1 = (const float*)d_in[9];
    const float* b1 = (const float*)d_in[10];
    const float* Wf = (const float*)d_in[11];
    const float* bf = (const float*)d_in[12];
    const float* g2 = (const float*)d_in[13];
    const float* b2 = (const float*)d_in[14];
    float* out = (float*)d_out;

    if (!g_init) {
        cudaFuncSetAttribute(k_gemm, cudaFuncAttributeMaxDynamicSharedMemorySize, SMEMB);
        for (int i = 0; i < 3; i++)
            cudaStreamCreateWithFlags(&g_st[i], cudaStreamNonBlocking);
        cudaEventCreateWithFlags(&evFork, cudaEventDisableTiming);
        cudaEventCreateWithFlags(&evP1, cudaEventDisableTiming);
        cudaEventCreateWithFlags(&evP2, cudaEventDisableTiming);
        cudaEventCreateWithFlags(&evP3, cudaEventDisableTiming);
        cudaEventCreateWithFlags(&evG,  cudaEventDisableTiming);
        for (int i = 0; i < 4; i++) {
            cudaEventCreateWithFlags(&evAT[i], cudaEventDisableTiming);
            cudaEventCreateWithFlags(&evPT[i], cudaEventDisableTiming);
        }
        cudaEventCreateWithFlags(&evC, cudaEventDisableTiming);
        g_init = true;
    }

    float *dA, *dPT8, *dO, *dc, *dFN, *dqbar, *dkbar;
    SYM(dA, g_A); SYM(dPT8, g_PT8); SYM(dO, g_O); SYM(dc, g_c);
    SYM(dFN, g_FN); SYM(dqbar, g_qbar); SYM(dkbar, g_kbar);
    bf16 *xh, *xl, *xTh, *xTl, *Gh, *Gl, *Wkh, *Wkl, *Wqh, *Wql, *Th, *Tl;
    bf16 *ATh, *ATl, *WvTh, *WvTl, *Mh, *Ml, *Wzh, *Wzl, *PTh, *PTl;
    bf16 *L1h, *L1l, *Wfh, *Wfl;
    SYM(xh, b_xh); SYM(xl, b_xl); SYM(xTh, b_xTh); SYM(xTl, b_xTl);
    SYM(Gh, b_Gh); SYM(Gl, b_Gl); SYM(Wkh, b_Wkh); SYM(Wkl, b_Wkl);
    SYM(Wqh, b_Wqh); SYM(Wql, b_Wql); SYM(Th, b_Th); SYM(Tl, b_Tl);
    SYM(ATh, b_ATh); SYM(ATl, b_ATl); SYM(WvTh, b_WvTh); SYM(WvTl, b_WvTl);
    SYM(Mh, b_Mh); SYM(Ml, b_Ml); SYM(Wzh, b_Wzh); SYM(Wzl, b_Wzl);
    SYM(PTh, b_PTh); SYM(PTl, b_PTl); SYM(L1h, b_L1h); SYM(L1l, b_L1l);
    SYM(Wfh, b_Wfh); SYM(Wfl, b_Wfl);

    const long long EE = (long long)E_DIM * E_DIM;
    dim3 tb(32, 8);
    cudaStream_t s0 = 0, s1 = g_st[0], s2 = g_st[1], s3 = g_st[2];
    cudaStream_t chainS[4] = { s0, s1, s2, s3 };

    cudaEventRecord(evFork, s0);
    cudaStreamWaitEvent(s1, evFork, 0);
    cudaStreamWaitEvent(s2, evFork, 0);
    cudaStreamWaitEvent(s3, evFork, 0);

    // ---- prep, 3-way parallel ----
    k_split<<<(int)(H_DIM * EE / 4 + 255) / 256, 256, 0, s1>>>((const float4*)Wk, (uint2*)Wkh, (uint2*)Wkl, (int)(H_DIM * EE / 4));
    k_split<<<(int)(H_DIM * EE / 4 + 255) / 256, 256, 0, s1>>>((const float4*)Wq, (uint2*)Wqh, (uint2*)Wql, (int)(H_DIM * EE / 4));
    k_usum1<<<dim3(4, 32), 256, 0, s1>>>(x);
    k_usum2<<<4, 256, 0, s1>>>();
    k_qkbar<<<dim3(E_DIM, H_DIM, 2), 256, 0, s1>>>(Wq, Wk, bq);
    cudaEventRecord(evP1, s1);
    k_trans_split<<<dim3(32, 32, H_DIM), tb, 0, s2>>>(Wv, WvTh, WvTl, E_DIM, E_DIM, EE, EE);
    k_split<<<(int)(H_DIM * EE / 4 + 255) / 256, 256, 0, s2>>>((const float4*)Wz, (uint2*)Wzh, (uint2*)Wzl, (int)(H_DIM * EE / 4));
    cudaEventRecord(evP2, s2);
    k_split<<<(int)(EE / 4 + 255) / 256, 256, 0, s3>>>((const float4*)Wf, (uint2*)Wfh, (uint2*)Wfl, (int)(EE / 4));
    k_split<<<(S_DIM * E_DIM / 4 + 255) / 256, 256, 0, s3>>>((const float4*)x, (uint2*)xh, (uint2*)xl, S_DIM * E_DIM / 4);
    cudaEventRecord(evP3, s3);

    // ---- s0: xT, G (split-K8 into dPT8 scratch, 512 CTAs), reduce ----
    k_trans_split<<<dim3(E_DIM / 32, S_DIM / 32, 1), tb, 0, s0>>>(x, xTh, xTl, S_DIM, E_DIM, 0, 0);
    { GemmP p{xTh, xTl, 512, S_DIM, xTh, xTl, 512, S_DIM,
              dPT8, 0, 0, EE, E_DIM, nullptr,
              nullptr, nullptr, nullptr, nullptr, 0, 1.0f, 512, 0};
      k_gemm<<<dim3(8, 8, 8), 128, SMEMB, s0>>>(p); }
    k_reduce_split<<<(int)(EE / 256), 256, 0, s0>>>(dPT8, 8, (int)EE, Gh, Gl);
    cudaEventRecord(evG, s0);

    // ---- four head chains: heads {0,1},{2,3},{4,5},{6,7} on s0..s3 ----
    for (int i = 0; i < 4; i++) {
        cudaStream_t s = chainS[i];
        const int hb = i * 2;
        if (s != s0) cudaStreamWaitEvent(s, evG, 0);
        if (s != s1) cudaStreamWaitEvent(s, evP1, 0);
        if (s != s2) cudaStreamWaitEvent(s, evP2, 0);
        { GemmP p{Wkh, Wkl, EE, E_DIM, Gh, Gl, 0, E_DIM,
                  0, Th, Tl, EE, E_DIM, nullptr,
                  nullptr, nullptr, nullptr, nullptr, 0, 1.0f, E_DIM, hb};
          k_gemm<<<dim3(8, 8, 2), 128, SMEMB, s>>>(p); }
        { GemmP p{Th, Tl, EE, E_DIM, Wqh, Wql, EE, E_DIM,
                  dA, 0, 0, EE, E_DIM, nullptr,
                  bk, dkbar, dqbar, bq, E_DIM, 0.03125f, E_DIM, hb};
          k_gemm<<<dim3(8, 8, 2), 128, SMEMB, s>>>(p); }
        k_rowstat<<<2 * E_DIM, 256, 0, s>>>(hb * E_DIM);
        k_transexp<<<dim3(32, 32, 2), tb, 0, s>>>(ATh, ATl, hb);
        cudaEventRecord(evAT[i], s);
        { GemmP p{WvTh, WvTl, EE, E_DIM, ATh, ATl, EE, E_DIM,
                  0, Mh, Ml, EE, E_DIM, nullptr,
                  nullptr, nullptr, nullptr, nullptr, 0, 1.0f, E_DIM, hb};
          k_gemm<<<dim3(8, 8, 2), 128, SMEMB, s>>>(p); }
        { GemmP p{Wzh, Wzl, E_DIM, HE_DIM, Mh, Ml, EE, E_DIM,
                  dPT8, 0, 0, EE, E_DIM, nullptr,
                  nullptr, nullptr, nullptr, nullptr, 0, 1.0f, E_DIM, hb};
          k_gemm<<<dim3(8, 8, 2), 128, SMEMB, s>>>(p); }
        cudaEventRecord(evPT[i], s);
    }

    // ---- s1: rvec/cvec (needs all AT halves; all evAT recorded above) ----
    cudaStreamWaitEvent(s1, evAT[0], 0);
    cudaStreamWaitEvent(s1, evAT[2], 0);
    cudaStreamWaitEvent(s1, evAT[3], 0);
    k_rvec<<<dim3(E_DIM, H_DIM), 256, 0, s1>>>(ATh, ATl, bv);
    k_cvec<<<E_DIM, 256, 0, s1>>>(Wz, bz);
    cudaEventRecord(evC, s1);

    // ---- s0 tail: join PT, reduce, O, LN1, FN, LN2 (R11 single-stream tail) ----
    cudaStreamWaitEvent(s0, evPT[1], 0);
    cudaStreamWaitEvent(s0, evPT[2], 0);
    cudaStreamWaitEvent(s0, evPT[3], 0);
    k_reduce_split<<<(int)(EE / 256), 256, 0, s0>>>(dPT8, 8, (int)EE, PTh, PTl);
    cudaStreamWaitEvent(s0, evP3, 0);   // xh/xl + Wf ready
    cudaStreamWaitEvent(s0, evC, 0);    // c vector ready
    { GemmP p{xh, xl, 0, E_DIM, PTh, PTl, 0, E_DIM,
              dO, 0, 0, 0, E_DIM, dc,
              nullptr, nullptr, nullptr, nullptr, 0, 1.0f, E_DIM, 0};
      k_gemm<<<dim3(8, 32, 1), 128, SMEMB, s0>>>(p); }
    k_ln1<<<S_DIM, 256, 0, s0>>>(x, g1, b1);
    { GemmP p{L1h, L1l, 0, E_DIM, Wfh, Wfl, 0, E_DIM,
              dFN, 0, 0, 0, E_DIM, bf,
              nullptr, nullptr, nullptr, nullptr, 0, 1.0f, E_DIM, 0};
      k_gemm<<<dim3(8, 32, 1), 128, SMEMB, s0>>>(p); }
    k_ln2<<<S_DIM, 256, 0, s0>>>(g2, b2, out);
}

// round 14
// speedup vs baseline: 1.0162x; 1.0162x over previous
#include <cuda_runtime.h>
#include <cuda_bf16.h>
#include <cstdint>

#define S_DIM 4096
#define E_DIM 1024
#define H_DIM 8
#define HE_DIM 8192
typedef __nv_bfloat16 bf16;

// ---------------- fp32 scratch ----------------------------------------------
__device__ float g_A  [(size_t)H_DIM * E_DIM * E_DIM];  // scaled+biased logits 32MB
__device__ float g_G4 [(size_t)4 * E_DIM * E_DIM];      // G split-K4 partials
__device__ float g_PT8[(size_t)H_DIM * E_DIM * E_DIM];  // PT partials
__device__ float g_O  [(size_t)S_DIM * E_DIM];
__device__ float g_LN1[(size_t)S_DIM * E_DIM];
__device__ float g_FN [(size_t)S_DIM * E_DIM];
__device__ float g_u32p[32 * E_DIM];
__device__ float g_u  [E_DIM];
__device__ float g_qbar[H_DIM * E_DIM];   // qbar + 4096*bq (folded)
__device__ float g_kbar[H_DIM * E_DIM];
__device__ float g_rowm[H_DIM * E_DIM];
__device__ float g_rowi[H_DIM * E_DIM];
__device__ float g_r  [H_DIM * E_DIM];
__device__ float g_c  [E_DIM];

// ---------------- bf16 hi/lo operand buffers ---------------------------------
__device__ bf16 b_xh [(size_t)S_DIM * E_DIM],  b_xl [(size_t)S_DIM * E_DIM];
__device__ bf16 b_xTh[(size_t)E_DIM * S_DIM],  b_xTl[(size_t)E_DIM * S_DIM];
__device__ bf16 b_Gh [(size_t)E_DIM * E_DIM],  b_Gl [(size_t)E_DIM * E_DIM];
__device__ bf16 b_Wkh[(size_t)H_DIM * E_DIM * E_DIM], b_Wkl[(size_t)H_DIM * E_DIM * E_DIM];
__device__ bf16 b_Wqh[(size_t)H_DIM * E_DIM * E_DIM], b_Wql[(size_t)H_DIM * E_DIM * E_DIM];
__device__ bf16 b_Th [(size_t)H_DIM * E_DIM * E_DIM], b_Tl [(size_t)H_DIM * E_DIM * E_DIM];
__device__ bf16 b_ATh[(size_t)H_DIM * E_DIM * E_DIM], b_ATl[(size_t)H_DIM * E_DIM * E_DIM];
__device__ bf16 b_WvTh[(size_t)H_DIM * E_DIM * E_DIM], b_WvTl[(size_t)H_DIM * E_DIM * E_DIM];
__device__ bf16 b_Mh [(size_t)H_DIM * E_DIM * E_DIM], b_Ml [(size_t)H_DIM * E_DIM * E_DIM];
__device__ bf16 b_Wzh[(size_t)H_DIM * E_DIM * E_DIM], b_Wzl[(size_t)H_DIM * E_DIM * E_DIM];
__device__ bf16 b_PTh[(size_t)E_DIM * E_DIM],  b_PTl[(size_t)E_DIM * E_DIM];
__device__ bf16 b_L1h[(size_t)S_DIM * E_DIM],  b_L1l[(size_t)S_DIM * E_DIM];
__device__ bf16 b_Wfh[(size_t)E_DIM * E_DIM],  b_Wfl[(size_t)E_DIM * E_DIM];

// ---------------- helpers ----------------------------------------------------
static __device__ __forceinline__ uint32_t s2u(const void* p) {
    uint32_t a;
    asm("{ .reg .u64 t; cvta.to.shared.u64 t, %1; cvt.u32.u64 %0, t; }"
        : "=r"(a) : "l"(p));
    return a;
}
static __device__ __forceinline__ uint32_t pack_bf(float a, float b) {
    uint32_t r;
    asm("cvt.rn.bf16x2.f32 %0, %1, %2;" : "=r"(r) : "f"(b), "f"(a));
    return r;
}
static __device__ __forceinline__ void ldsm4(uint32_t* r, uint32_t addr) {
    asm volatile("ldmatrix.sync.aligned.m8n8.x4.shared.b16 {%0,%1,%2,%3}, [%4];"
                 : "=r"(r[0]), "=r"(r[1]), "=r"(r[2]), "=r"(r[3]) : "r"(addr));
}
static __device__ __forceinline__ void mma16816(float* d, const uint32_t* a,
                                                uint32_t b0, uint32_t b1) {
    asm volatile(
        "mma.sync.aligned.m16n8k16.row.col.f32.bf16.bf16.f32 "
        "{%0,%1,%2,%3},{%4,%5,%6,%7},{%8,%9},{%0,%1,%2,%3};"
        : "+f"(d[0]), "+f"(d[1]), "+f"(d[2]), "+f"(d[3])
        : "r"(a[0]), "r"(a[1]), "r"(a[2]), "r"(a[3]), "r"(b0), "r"(b1));
}
static __device__ __forceinline__ void cp16(uint32_t dst, const void* src) {
    asm volatile("cp.async.cg.shared.global [%0], [%1], 16;"
                 :: "r"(dst), "l"(src));
}

// ============================================================================
// bf16 hi/lo cp.async GEMM (NT): C = (A.B^T + eA⊗eC + eB⊗eD)*alpha + bn
// CTA 128x128, BK=32, 128 threads (4 warps 2x2, warp tile 64x64), 3 stages.
// (R7/R10/R11 core — best measured config)
// ============================================================================
#define STAGEB 32768
#define SMEMB  (3 * STAGEB)

struct GemmP {
    const bf16 *Ah, *Al; long long As; int lda;
    const bf16 *Bh, *Bl; long long Bs; int ldb;
    float* Cf; bf16 *Ch, *Cl; long long Cs; int ldc;
    const float* bn;
    const float *eA, *eB, *eC, *eD; int eS;
    float alpha;
    int K;
    int zoff;
};

static __device__ __forceinline__ void issue_stage(
    uint32_t sbase, int slot,
    const bf16* __restrict__ Ah, const bf16* __restrict__ Al, int lda,
    const bf16* __restrict__ Bh, const bf16* __restrict__ Bl, int ldb,
    int k0, int tid) {
    uint32_t st = sbase + (uint32_t)slot * STAGEB;
#pragma unroll
    for (int i = 0; i < 16; i++) {
        int idx = tid + i * 128;              // 0..2047
        int half = idx >> 10;                 // 0 = A, 1 = B
        int r = (idx >> 3) & 127;
        int c = idx & 7;                      // chunk: 0-3 hi, 4-7 lo
        const bf16* base;
        int ld;
        if (half == 0) { base = (c < 4) ? Ah : Al; ld = lda; }
        else           { base = (c < 4) ? Bh : Bl; ld = ldb; }
        const char* src = (const char*)(base + (size_t)r * ld + k0) + (c & 3) * 16;
        uint32_t dst = st + (uint32_t)half * 16384u + (uint32_t)r * 128u
                     + (uint32_t)((c ^ (r & 7)) << 4);
        cp16(dst, src);
    }
}

__global__ __launch_bounds__(128, 2) void k_gemm(GemmP p) {
    extern __shared__ char smem[];
    const int tid = threadIdx.x;
    const int w = tid >> 5, l = tid & 31;
    const int wm = (w >> 1) * 64, wn = (w & 1) * 64;
    const int m0 = blockIdx.y * 128, n0 = blockIdx.x * 128;
    const int z = blockIdx.z + p.zoff;
    const uint32_t s0 = s2u(smem);

    const bf16* Abh = p.Ah + (size_t)z * p.As + (size_t)m0 * p.lda;
    const bf16* Abl = p.Al + (size_t)z * p.As + (size_t)m0 * p.lda;
    const bf16* Bbh = p.Bh + (size_t)z * p.Bs + (size_t)n0 * p.ldb;
    const bf16* Bbl = p.Bl + (size_t)z * p.Bs + (size_t)n0 * p.ldb;

    const uint32_t axor = (uint32_t)(l & 7);
    const uint32_t arow = (uint32_t)(wm + (l & 15));
    const uint32_t asel = (uint32_t)(l >> 4);
    const uint32_t brow = (uint32_t)(wn + (l & 7) + ((l >> 4) & 1) * 8);
    const uint32_t bsel = (uint32_t)((l >> 3) & 1);

    float acc[4][8][4];
#pragma unroll
    for (int t = 0; t < 4; t++)
#pragma unroll
        for (int j = 0; j < 8; j++)
#pragma unroll
            for (int r = 0; r < 4; r++) acc[t][j][r] = 0.f;

    const int NC = p.K >> 5;
    issue_stage(s0, 0, Abh, Abl, p.lda, Bbh, Bbl, p.ldb, 0, tid);
    asm volatile("cp.async.commit_group;" ::: "memory");
    issue_stage(s0, 1, Abh, Abl, p.lda, Bbh, Bbl, p.ldb, 32, tid);
    asm volatile("cp.async.commit_group;" ::: "memory");

    for (int c = 0; c < NC; c++) {
        asm volatile("cp.async.wait_group 1;" ::: "memory");
        __syncthreads();
        if (c + 2 < NC)
            issue_stage(s0, (c + 2) % 3, Abh, Abl, p.lda, Bbh, Bbl, p.ldb,
                        (c + 2) * 32, tid);
        asm volatile("cp.async.commit_group;" ::: "memory");

        uint32_t st = s0 + (uint32_t)(c % 3) * STAGEB;
#pragma unroll
        for (int ks = 0; ks < 2; ks++) {
            uint32_t bh[4][4], bl[4][4];
#pragma unroll
            for (int jp = 0; jp < 4; jp++) {
                uint32_t ba = st + 16384u + (brow + jp * 16u) * 128u
                            + (((2u * ks + bsel) ^ axor) << 4);
                ldsm4(bh[jp], ba);
                ldsm4(bl[jp], ba ^ 0x40u);
            }
#pragma unroll
            for (int t = 0; t < 4; t++) {
                uint32_t ah[4], al[4];
                uint32_t aa = st + (arow + t * 16u) * 128u
                            + (((2u * ks + asel) ^ axor) << 4);
                ldsm4(ah, aa);
                ldsm4(al, aa ^ 0x40u);
#pragma unroll
                for (int j = 0; j < 8; j++) {
                    uint32_t b0h = bh[j >> 1][(j & 1) * 2];
                    uint32_t b1h = bh[j >> 1][(j & 1) * 2 + 1];
                    uint32_t b0l = bl[j >> 1][(j & 1) * 2];
                    uint32_t b1l = bl[j >> 1][(j & 1) * 2 + 1];
                    mma16816(acc[t][j], ah, b0h, b1h);
                    mma16816(acc[t][j], ah, b0l, b1l);
                    mma16816(acc[t][j], al, b0h, b1h);
                }
            }
        }
    }

    float* Cf = p.Cf ? p.Cf + (size_t)z * p.Cs : (float*)0;
    bf16* Ch = p.Ch ? p.Ch + (size_t)z * p.Cs : (bf16*)0;
    bf16* Cl = p.Cl ? p.Cl + (size_t)z * p.Cs : (bf16*)0;
    const float* bn = p.bn;
    const float* eA = p.eA ? p.eA + (size_t)z * p.eS : (const float*)0;
    const float* eB = p.eB ? p.eB + (size_t)z * p.eS : (const float*)0;
    const float* eC = p.eC ? p.eC + (size_t)z * p.eS : (const float*)0;
    const float* eD = p.eD ? p.eD + (size_t)z * p.eS : (const float*)0;
    const float alpha = p.alpha;
#pragma unroll
    for (int t = 0; t < 4; t++) {
        int m = m0 + wm + t * 16 + (l >> 2);
#pragma unroll
        for (int j = 0; j < 8; j++) {
            int n = n0 + wn + j * 8 + (l & 3) * 2;
#pragma unroll
            for (int h2 = 0; h2 < 2; h2++) {
                float v0 = acc[t][j][h2 * 2], v1 = acc[t][j][h2 * 2 + 1];
                int mr = m + h2 * 8;
                if (eA) {
                    float a = eA[mr], b = eB[mr];
                    v0 += a * eC[n]     + b * eD[n];
                    v1 += a * eC[n + 1] + b * eD[n + 1];
                }
                v0 *= alpha; v1 *= alpha;
                if (bn) { v0 += bn[n]; v1 += bn[n + 1]; }
                if (Cf) *(float2*)(Cf + (size_t)mr * p.ldc + n) = make_float2(v0, v1);
                if (Ch) {
                    uint32_t hh = pack_bf(v0, v1);
                    *(uint32_t*)((char*)Ch + ((size_t)mr * p.ldc + n) * 2) = hh;
                    float l0 = v0 - __uint_as_float(hh << 16);
                    float l1 = v1 - __uint_as_float(hh & 0xFFFF0000u);
                    *(uint32_t*)((char*)Cl + ((size_t)mr * p.ldc + n) * 2) = pack_bf(l0, l1);
                }
            }
        }
    }
}

// ---------------- reductions -------------------------------------------------
static __device__ __forceinline__ float blockReduceSum256(float v) {
    __shared__ float sb[8];
#pragma unroll
    for (int o = 16; o > 0; o >>= 1) v += __shfl_xor_sync(0xffffffffu, v, o);
    __syncthreads();
    if ((threadIdx.x & 31) == 0) sb[threadIdx.x >> 5] = v;
    __syncthreads();
    float r = sb[0];
#pragma unroll
    for (int i = 1; i < 8; i++) r += sb[i];
    return r;
}
static __device__ __forceinline__ float blockReduceMax256(float v) {
    __shared__ float sb[8];
#pragma unroll
    for (int o = 16; o > 0; o >>= 1) v = fmaxf(v, __shfl_xor_sync(0xffffffffu, v, o));
    __syncthreads();
    if ((threadIdx.x & 31) == 0) sb[threadIdx.x >> 5] = v;
    __syncthreads();
    float r = sb[0];
#pragma unroll
    for (int i = 1; i < 8; i++) r = fmaxf(r, sb[i]);
    return r;
}

// ---------------- conversion / transpose kernels ------------------------------
__global__ void k_split(const float4* __restrict__ src, uint2* __restrict__ hi,
                        uint2* __restrict__ lo, int n4) {
    int i = blockIdx.x * 256 + threadIdx.x;
    if (i >= n4) return;
    float4 v = src[i];
    uint32_t h0 = pack_bf(v.x, v.y), h1 = pack_bf(v.z, v.w);
    float lx = v.x - __uint_as_float(h0 << 16);
    float ly = v.y - __uint_as_float(h0 & 0xFFFF0000u);
    float lz = v.z - __uint_as_float(h1 << 16);
    float lw = v.w - __uint_as_float(h1 & 0xFFFF0000u);
    hi[i] = make_uint2(h0, h1);
    lo[i] = make_uint2(pack_bf(lx, ly), pack_bf(lz, lw));
}

__global__ void k_trans_split(const float* __restrict__ src,
                              bf16* __restrict__ hi, bf16* __restrict__ lo,
                              int R, int C, long long ss, long long ds) {
    __shared__ float t[32][33];
    src += (size_t)blockIdx.z * ss;
    hi += (size_t)blockIdx.z * ds;
    lo += (size_t)blockIdx.z * ds;
    int c0 = blockIdx.x * 32, r0 = blockIdx.y * 32;
#pragma unroll
    for (int i = 0; i < 32; i += 8)
        t[threadIdx.y + i][threadIdx.x] =
            src[(size_t)(r0 + threadIdx.y + i) * C + c0 + threadIdx.x];
    __syncthreads();
#pragma unroll
    for (int i = 0; i < 32; i += 8) {
        float v = t[threadIdx.x][threadIdx.y + i];
        bf16 h = __float2bfloat16_rn(v);
        size_t o = (size_t)(c0 + threadIdx.y + i) * R + r0 + threadIdx.x;
        hi[o] = h;
        lo[o] = __float2bfloat16_rn(v - __bfloat162float(h));
    }
}

// row max + 1/sum(exp) of logits, rows [rowbase, rowbase+grid)
__global__ __launch_bounds__(256, 4) void k_rowstat(int rowbase) {
    int row = rowbase + blockIdx.x;
    const float* p = g_A + (size_t)row * E_DIM;
    int tid = threadIdx.x;
    float v[4];
    float m = -1e30f;
#pragma unroll
    for (int i = 0; i < 4; i++) { v[i] = p[tid + i * 256]; m = fmaxf(m, v[i]); }
    m = blockReduceMax256(m);
    float s = 0;
#pragma unroll
    for (int i = 0; i < 4; i++) s += __expf(v[i] - m);
    s = blockReduceSum256(s);
    if (tid == 0) { g_rowm[row] = m; g_rowi[row] = 1.0f / s; }
}

// AT[f,e] = exp(A[e,f]-m[e])*inv[e], hi/lo split, heads [hbase, hbase+grid.z)
__global__ void k_transexp(bf16* __restrict__ hi, bf16* __restrict__ lo, int hbase) {
    __shared__ float t[32][33];
    int h = hbase + blockIdx.z;
    const float* src = g_A + (size_t)h * E_DIM * E_DIM;
    bf16* hih = hi + (size_t)h * E_DIM * E_DIM;
    bf16* loh = lo + (size_t)h * E_DIM * E_DIM;
    int f0 = blockIdx.x * 32, e0 = blockIdx.y * 32;
#pragma unroll
    for (int i = 0; i < 32; i += 8) {
        int e = e0 + threadIdx.y + i;
        float m = g_rowm[h * E_DIM + e], inv = g_rowi[h * E_DIM + e];
        float v = src[(size_t)e * E_DIM + f0 + threadIdx.x];
        t[threadIdx.y + i][threadIdx.x] = __expf(v - m) * inv;
    }
    __syncthreads();
#pragma unroll
    for (int i = 0; i < 32; i += 8) {
        float v = t[threadIdx.x][threadIdx.y + i];
        bf16 hh = __float2bfloat16_rn(v);
        size_t o = (size_t)(f0 + threadIdx.y + i) * E_DIM + e0 + threadIdx.x;
        hih[o] = hh;
        loh[o] = __float2bfloat16_rn(v - __bfloat162float(hh));
    }
}

__global__ void k_reduce_split(const float* __restrict__ src, int Z, int total,
                               bf16* __restrict__ hi, bf16* __restrict__ lo) {
    int i = blockIdx.x * 256 + threadIdx.x;
    if (i >= total) return;
    float s = 0;
    for (int zz = 0; zz < Z; zz++) s += src[(size_t)zz * total + i];
    bf16 h = __float2bfloat16_rn(s);
    hi[i] = h;
    lo[i] = __float2bfloat16_rn(s - __bfloat162float(h));
}

// ---------------- small algebra kernels ---------------------------------------
__global__ void k_usum1(const float* __restrict__ x) {
    int e = blockIdx.x * 256 + threadIdx.x;
    int zc = blockIdx.y;
    float s = 0;
    for (int si = zc * 128; si < zc * 128 + 128; si++) s += x[(size_t)si * E_DIM + e];
    g_u32p[zc * E_DIM + e] = s;
}
__global__ void k_usum2() {
    int e = blockIdx.x * 256 + threadIdx.x;
    float s = 0;
    for (int zc = 0; zc < 32; zc++) s += g_u32p[zc * E_DIM + e];
    g_u[e] = s;
}
__global__ void k_qkbar(const float* __restrict__ Wq, const float* __restrict__ Wk,
                        const float* __restrict__ bq) {
    int f = blockIdx.x, h = blockIdx.y;
    const float* Wrow = (blockIdx.z == 0 ? Wq : Wk) + ((size_t)h * E_DIM + f) * E_DIM;
    float s = 0;
    for (int i = threadIdx.x; i < E_DIM; i += 256) s += g_u[i] * Wrow[i];
    s = blockReduceSum256(s);
    if (threadIdx.x == 0) {
        if (blockIdx.z == 0) g_qbar[h * E_DIM + f] = s + 4096.0f * bq[h * E_DIM + f];
        else                 g_kbar[h * E_DIM + f] = s;
    }
}

__global__ void k_rvec(const bf16* __restrict__ ATh, const bf16* __restrict__ ATl,
                       const float* __restrict__ bv) {
    int f = blockIdx.x, h = blockIdx.y;
    const bf16* ph = ATh + ((size_t)h * E_DIM + f) * E_DIM;
    const bf16* pl = ATl + ((size_t)h * E_DIM + f) * E_DIM;
    const float* bvh = bv + h * E_DIM;
    float s = 0;
    for (int e = threadIdx.x; e < E_DIM; e += 256)
        s += (__bfloat162float(ph[e]) + __bfloat162float(pl[e])) * bvh[e];
    s = blockReduceSum256(s);
    if (threadIdx.x == 0) g_r[h * E_DIM + f] = s;
}
__global__ void k_cvec(const float* __restrict__ Wz, const float* __restrict__ bz) {
    int o = blockIdx.x;
    const float* wrow = Wz + (size_t)o * HE_DIM;
    float s = 0;
    for (int i = threadIdx.x; i < HE_DIM; i += 256) s += g_r[i] * wrow[i];
    s = blockReduceSum256(s);
    if (threadIdx.x == 0) g_c[o] = bz[o] + s;
}

// LN1 = LN(O)*g1+b1 + x  (writes fp32 + bf16 hi/lo)
__global__ __launch_bounds__(256, 4)
void k_ln1(const float* __restrict__ x, const float* __restrict__ g,
           const float* __restrict__ b) {
    const size_t row = blockIdx.x;
    const int tid = threadIdx.x;
    const float* p = g_O + row * E_DIM;
    float v[4];
    float s = 0.f;
#pragma unroll
    for (int i = 0; i < 4; i++) { v[i] = p[tid + i * 256]; s += v[i]; }
    const float mean = blockReduceSum256(s) * (1.0f / E_DIM);
    float q = 0.f;
#pragma unroll
    for (int i = 0; i < 4; i++) { const float d = v[i] - mean; q += d * d; }
    const float var = blockReduceSum256(q) * (1.0f / E_DIM);
    const float rstd = rsqrtf(var + 1e-5f);
#pragma unroll
    for (int i = 0; i < 4; i++) {
        const int idx = tid + i * 256;
        float o = (v[i] - mean) * rstd * g[idx] + b[idx] + x[row * E_DIM + idx];
        g_LN1[row * E_DIM + idx] = o;
        bf16 h = __float2bfloat16_rn(o);
        b_L1h[row * E_DIM + idx] = h;
        b_L1l[row * E_DIM + idx] = __float2bfloat16_rn(o - __bfloat162float(h));
    }
}

__global__ __launch_bounds__(256, 4)
void k_ln2(const float* __restrict__ g, const float* __restrict__ b,
           float* __restrict__ out) {
    const size_t row = blockIdx.x;
    const int tid = threadIdx.x;
    const float* p = g_FN + row * E_DIM;
    float v[4];
    float s = 0.f;
#pragma unroll
    for (int i = 0; i < 4; i++) { v[i] = p[tid + i * 256]; s += v[i]; }
    const float mean = blockReduceSum256(s) * (1.0f / E_DIM);
    float q = 0.f;
#pragma unroll
    for (int i = 0; i < 4; i++) { const float d = v[i] - mean; q += d * d; }
    const float var = blockReduceSum256(q) * (1.0f / E_DIM);
    const float rstd = rsqrtf(var + 1e-5f);
#pragma unroll
    for (int i = 0; i < 4; i++) {
        const int idx = tid + i * 256;
        out[row * E_DIM + idx] =
            (v[i] - mean) * rstd * g[idx] + b[idx] + g_LN1[row * E_DIM + idx];
    }
}

// ============================================================================
// Launch — R11 schedule + split prep events (evPW for T, evP1 for logits)
// (every cudaEventRecord precedes its cudaStreamWaitEvent in host order)
// ============================================================================
#define SYM(v, s) cudaGetSymbolAddress((void**)&v, s)

static cudaStream_t g_st[3];          // s1, s2, s3 (s0 = default)
static cudaEvent_t evFork, evPW, evP1, evP2, evP3, evG;
static cudaEvent_t evAT[4], evPT[4], evC;
static bool g_init = false;

extern "C" void kernel_launch(void* const* d_in, const int* in_sizes, int n_in,
                              void* d_out, int out_size) {
    (void)in_sizes; (void)n_in; (void)out_size;
    const float* x  = (const float*)d_in[0];
    const float* Wq = (const float*)d_in[1];
    const float* bq = (const float*)d_in[2];
    const float* Wk = (const float*)d_in[3];
    const float* bk = (const float*)d_in[4];
    const float* Wv = (const float*)d_in[5];
    const float* bv = (const float*)d_in[6];
    const float* Wz = (const float*)d_in[7];
    const float* bz = (const float*)d_in[8];
    const float* g1 = (const float*)d_in[9];
    const float* b1 = (const float*)d_in[10];
    const float* Wf = (const float*)d_in[11];
    const float* bf = (const float*)d_in[12];
    const float* g2 = (const float*)d_in[13];
    const float* b2 = (const float*)d_in[14];
    float* out = (float*)d_out;

    if (!g_init) {
        cudaFuncSetAttribute(k_gemm, cudaFuncAttributeMaxDynamicSharedMemorySize, SMEMB);
        for (int i = 0; i < 3; i++)
            cudaStreamCreateWithFlags(&g_st[i], cudaStreamNonBlocking);
        cudaEventCreateWithFlags(&evFork, cudaEventDisableTiming);
        cudaEventCreateWithFlags(&evPW, cudaEventDisableTiming);
        cudaEventCreateWithFlags(&evP1, cudaEventDisableTiming);
        cudaEventCreateWithFlags(&evP2, cudaEventDisableTiming);
        cudaEventCreateWithFlags(&evP3, cudaEventDisableTiming);
        cudaEventCreateWithFlags(&evG,  cudaEventDisableTiming);
        for (int i = 0; i < 4; i++) {
            cudaEventCreateWithFlags(&evAT[i], cudaEventDisableTiming);
            cudaEventCreateWithFlags(&evPT[i], cudaEventDisableTiming);
        }
        cudaEventCreateWithFlags(&evC, cudaEventDisableTiming);
        g_init = true;
    }

    float *dA, *dG4, *dPT8, *dO, *dc, *dFN, *dqbar, *dkbar;
    SYM(dA, g_A); SYM(dG4, g_G4); SYM(dPT8, g_PT8); SYM(dO, g_O); SYM(dc, g_c);
    SYM(dFN, g_FN); SYM(dqbar, g_qbar); SYM(dkbar, g_kbar);
    bf16 *xh, *xl, *xTh, *xTl, *Gh, *Gl, *Wkh, *Wkl, *Wqh, *Wql, *Th, *Tl;
    bf16 *ATh, *ATl, *WvTh, *WvTl, *Mh, *Ml, *Wzh, *Wzl, *PTh, *PTl;
    bf16 *L1h, *L1l, *Wfh, *Wfl;
    SYM(xh, b_xh); SYM(xl, b_xl); SYM(xTh, b_xTh); SYM(xTl, b_xTl);
    SYM(Gh, b_Gh); SYM(Gl, b_Gl); SYM(Wkh, b_Wkh); SYM(Wkl, b_Wkl);
    SYM(Wqh, b_Wqh); SYM(Wql, b_Wql); SYM(Th, b_Th); SYM(Tl, b_Tl);
    SYM(ATh, b_ATh); SYM(ATl, b_ATl); SYM(WvTh, b_WvTh); SYM(WvTl, b_WvTl);
    SYM(Mh, b_Mh); SYM(Ml, b_Ml); SYM(Wzh, b_Wzh); SYM(Wzl, b_Wzl);
    SYM(PTh, b_PTh); SYM(PTl, b_PTl); SYM(L1h, b_L1h); SYM(L1l, b_L1l);
    SYM(Wfh, b_Wfh); SYM(Wfl, b_Wfl);

    const long long EE = (long long)E_DIM * E_DIM;
    dim3 tb(32, 8);
    cudaStream_t s0 = 0, s1 = g_st[0], s2 = g_st[1], s3 = g_st[2];
    cudaStream_t chainS[4] = { s0, s1, s2, s3 };

    cudaEventRecord(evFork, s0);
    cudaStreamWaitEvent(s1, evFork, 0);
    cudaStreamWaitEvent(s2, evFork, 0);
    cudaStreamWaitEvent(s3, evFork, 0);

    // ---- prep, 3-way parallel ----
    k_split<<<(int)(H_DIM * EE / 4 + 255) / 256, 256, 0, s1>>>((const float4*)Wk, (uint2*)Wkh, (uint2*)Wkl, (int)(H_DIM * EE / 4));
    k_split<<<(int)(H_DIM * EE / 4 + 255) / 256, 256, 0, s1>>>((const float4*)Wq, (uint2*)Wqh, (uint2*)Wql, (int)(H_DIM * EE / 4));
    cudaEventRecord(evPW, s1);                     // W splits done (enough for T)
    k_usum1<<<dim3(4, 32), 256, 0, s1>>>(x);
    k_usum2<<<4, 256, 0, s1>>>();
    k_qkbar<<<dim3(E_DIM, H_DIM, 2), 256, 0, s1>>>(Wq, Wk, bq);
    cudaEventRecord(evP1, s1);                     // qkbar done (needed by logits)
    k_trans_split<<<dim3(32, 32, H_DIM), tb, 0, s2>>>(Wv, WvTh, WvTl, E_DIM, E_DIM, EE, EE);
    k_split<<<(int)(H_DIM * EE / 4 + 255) / 256, 256, 0, s2>>>((const float4*)Wz, (uint2*)Wzh, (uint2*)Wzl, (int)(H_DIM * EE / 4));
    cudaEventRecord(evP2, s2);
    k_split<<<(int)(EE / 4 + 255) / 256, 256, 0, s3>>>((const float4*)Wf, (uint2*)Wfh, (uint2*)Wfl, (int)(EE / 4));
    k_split<<<(S_DIM * E_DIM / 4 + 255) / 256, 256, 0, s3>>>((const float4*)x, (uint2*)xh, (uint2*)xl, S_DIM * E_DIM / 4);
    cudaEventRecord(evP3, s3);

    // ---- s0: xT, G (split-K4, as in R11), reduce ----
    k_trans_split<<<dim3(E_DIM / 32, S_DIM / 32, 1), tb, 0, s0>>>(x, xTh, xTl, S_DIM, E_DIM, 0, 0);
    { GemmP p{xTh, xTl, 1024, S_DIM, xTh, xTl, 1024, S_DIM,
              dG4, 0, 0, EE, E_DIM, nullptr,
              nullptr, nullptr, nullptr, nullptr, 0, 1.0f, 1024, 0};
      k_gemm<<<dim3(8, 8, 4), 128, SMEMB, s0>>>(p); }
    k_reduce_split<<<(int)(EE / 256), 256, 0, s0>>>(dG4, 4, (int)EE, Gh, Gl);
    cudaEventRecord(evG, s0);

    // ---- four head chains: heads {0,1},{2,3},{4,5},{6,7} on s0..s3 ----
    for (int i = 0; i < 4; i++) {
        cudaStream_t s = chainS[i];
        const int hb = i * 2;
        if (s != s0) cudaStreamWaitEvent(s, evG, 0);
        if (s != s1) cudaStreamWaitEvent(s, evPW, 0);   // only W splits gate T
        if (s != s2) cudaStreamWaitEvent(s, evP2, 0);   // WvT/Wz (for M/PT)
        // T_h = Wk_h @ G
        { GemmP p{Wkh, Wkl, EE, E_DIM, Gh, Gl, 0, E_DIM,
                  0, Th, Tl, EE, E_DIM, nullptr,
                  nullptr, nullptr, nullptr, nullptr, 0, 1.0f, E_DIM, hb};
          k_gemm<<<dim3(8, 8, 2), 128, SMEMB, s>>>(p); }
        // logits needs qkbar -> wait evP1 just before it
        if (s != s1) cudaStreamWaitEvent(s, evP1, 0);
        { GemmP p{Th, Tl, EE, E_DIM, Wqh, Wql, EE, E_DIM,
                  dA, 0, 0, EE, E_DIM, nullptr,
                  bk, dkbar, dqbar, bq, E_DIM, 0.03125f, E_DIM, hb};
          k_gemm<<<dim3(8, 8, 2), 128, SMEMB, s>>>(p); }
        k_rowstat<<<2 * E_DIM, 256, 0, s>>>(hb * E_DIM);
        k_transexp<<<dim3(32, 32, 2), tb, 0, s>>>(ATh, ATl, hb);
        cudaEventRecord(evAT[i], s);
        // M_h = Wv_h^T @ A_h
        { GemmP p{WvTh, WvTl, EE, E_DIM, ATh, ATl, EE, E_DIM,
                  0, Mh, Ml, EE, E_DIM, nullptr,
                  nullptr, nullptr, nullptr, nullptr, 0, 1.0f, E_DIM, hb};
          k_gemm<<<dim3(8, 8, 2), 128, SMEMB, s>>>(p); }
        // PT8_h = Wz_h @ M_h
        { GemmP p{Wzh, Wzl, E_DIM, HE_DIM, Mh, Ml, EE, E_DIM,
                  dPT8, 0, 0, EE, E_DIM, nullptr,
                  nullptr, nullptr, nullptr, nullptr, 0, 1.0f, E_DIM, hb};
          k_gemm<<<dim3(8, 8, 2), 128, SMEMB, s>>>(p); }
        cudaEventRecord(evPT[i], s);
    }

    // ---- s1: rvec/cvec (needs all AT halves; all evAT recorded above) ----
    cudaStreamWaitEvent(s1, evAT[0], 0);
    cudaStreamWaitEvent(s1, evAT[2], 0);
    cudaStreamWaitEvent(s1, evAT[3], 0);
    k_rvec<<<dim3(E_DIM, H_DIM), 256, 0, s1>>>(ATh, ATl, bv);
    k_cvec<<<E_DIM, 256, 0, s1>>>(Wz, bz);
    cudaEventRecord(evC, s1);

    // ---- s0 tail: join PT, reduce, O, LN1, FN, LN2 (R11 single-stream tail) ----
    cudaStreamWaitEvent(s0, evPT[1], 0);
    cudaStreamWaitEvent(s0, evPT[2], 0);
    cudaStreamWaitEvent(s0, evPT[3], 0);
    k_reduce_split<<<(int)(EE / 256), 256, 0, s0>>>(dPT8, 8, (int)EE, PTh, PTl);
    cudaStreamWaitEvent(s0, evP3, 0);   // xh/xl + Wf ready
    cudaStreamWaitEvent(s0, evC, 0);    // c vector ready
    { GemmP p{xh, xl, 0, E_DIM, PTh, PTl, 0, E_DIM,
              dO, 0, 0, 0, E_DIM, dc,
              nullptr, nullptr, nullptr, nullptr, 0, 1.0f, E_DIM, 0};
      k_gemm<<<dim3(8, 32, 1), 128, SMEMB, s0>>>(p); }
    k_ln1<<<S_DIM, 256, 0, s0>>>(x, g1, b1);
    { GemmP p{L1h, L1l, 0, E_DIM, Wfh, Wfl, 0, E_DIM,
              dFN, 0, 0, 0, E_DIM, bf,
              nullptr, nullptr, nullptr, nullptr, 0, 1.0f, E_DIM, 0};
      k_gemm<<<dim3(8, 32, 1), 128, SMEMB, s0>>>(p); }
    k_ln2<<<S_DIM, 256, 0, s0>>>(g2, b2, out);
}